// round 1
// baseline (speedup 1.0000x reference)
#include <cuda_runtime.h>

#define D 64
#define MAX_TOKENS 4096

// Scratch (no cudaMalloc allowed)
__device__ float g_emb[MAX_TOKENS * D];
__device__ float g_x2[MAX_TOKENS];
__device__ float g_rinv[MAX_TOKENS];
__device__ int   g_is64;

// ---------------------------------------------------------------------------
// Detect whether token_ids buffer is int64 or int32.
// For little-endian int64 with values in [0, 2^31), every odd 32-bit word is 0.
// Scan only the first n_ids words (safe for both layouts).
// ---------------------------------------------------------------------------
__global__ void detect_kernel(const int* __restrict__ ids, int n_words) {
    __shared__ int any;
    if (threadIdx.x == 0) any = 0;
    __syncthreads();
    for (int i = threadIdx.x * 2 + 1; i < n_words; i += 2 * blockDim.x) {
        if (ids[i] != 0) any = 1;
    }
    __syncthreads();
    if (threadIdx.x == 0) g_is64 = any ? 0 : 1;
}

// ---------------------------------------------------------------------------
// Prep: gather embedding rows, project to Poincare ball, compute x2 and
// 1/(1 - x2). One warp per token.
// ---------------------------------------------------------------------------
__global__ void prep_kernel(const void* __restrict__ ids_raw,
                            const float* __restrict__ W,
                            int n_ids, int num_tok) {
    int warp = (blockIdx.x * blockDim.x + threadIdx.x) >> 5;
    int lane = threadIdx.x & 31;
    if (warp >= n_ids) return;

    long long id;
    if (g_is64) id = ((const long long*)ids_raw)[warp];
    else        id = (long long)((const int*)ids_raw)[warp];
    if (id < 0) id = 0;
    if (id > (long long)(num_tok - 1)) id = num_tok - 1;

    const float* row = W + (size_t)id * D;
    float v0 = row[lane];
    float v1 = row[lane + 32];
    float s = v0 * v0 + v1 * v1;
#pragma unroll
    for (int o = 16; o; o >>= 1) s += __shfl_xor_sync(0xffffffffu, s, o);

    const float max_norm = 1.0f - 1e-5f;
    float norm = sqrtf(s);
    float f = (norm > max_norm) ? (max_norm / fmaxf(norm, 1e-12f)) : 1.0f;
    v0 *= f; v1 *= f;

    g_emb[warp * D + lane]      = v0;
    g_emb[warp * D + lane + 32] = v1;

    float s2 = v0 * v0 + v1 * v1;
#pragma unroll
    for (int o = 16; o; o >>= 1) s2 += __shfl_xor_sync(0xffffffffu, s2, o);

    if (lane == 0) {
        g_x2[warp]   = s2;
        g_rinv[warp] = 1.0f / (1.0f - s2);
    }
}

// ---------------------------------------------------------------------------
// Main: per CTA, one 64x64 tile of the SxS bias matrix for one batch.
// smem tiles stored k-major (As[k][row]) so the inner loop does vectorized
// LDS.128 loads for both fragments.
// ---------------------------------------------------------------------------
__global__ __launch_bounds__(256)
void bias_kernel(const float* __restrict__ scale_p,
                 float* __restrict__ out, int S) {
    __shared__ float As[D][68];
    __shared__ float Bs[D][68];
    __shared__ float sx2i[64], sx2j[64], sri[64], srj[64];

    int b  = blockIdx.z;
    int i0 = blockIdx.y * 64;
    int j0 = blockIdx.x * 64;
    int base = b * S;
    int t = threadIdx.x;

    // Load + transpose 64x64 tiles into smem (coalesced global float4 reads).
    {
        int row = t >> 2, q = t & 3;
        const float* ap = g_emb + (size_t)(base + i0 + row) * D + q * 16;
        const float* bp = g_emb + (size_t)(base + j0 + row) * D + q * 16;
#pragma unroll
        for (int i = 0; i < 4; i++) {
            float4 va = *(const float4*)(ap + i * 4);
            float4 vb = *(const float4*)(bp + i * 4);
            int k = q * 16 + i * 4;
            As[k][row] = va.x; As[k + 1][row] = va.y;
            As[k + 2][row] = va.z; As[k + 3][row] = va.w;
            Bs[k][row] = vb.x; Bs[k + 1][row] = vb.y;
            Bs[k + 2][row] = vb.z; Bs[k + 3][row] = vb.w;
        }
        if (t < 64) {
            sx2i[t] = g_x2[base + i0 + t];
            sri[t]  = g_rinv[base + i0 + t];
            sx2j[t] = g_x2[base + j0 + t];
            srj[t]  = g_rinv[base + j0 + t];
        }
    }
    __syncthreads();

    int tx = t & 15, ty = t >> 4;
    int r0 = ty * 4, c0 = tx * 4;

    float acc[4][4];
#pragma unroll
    for (int i = 0; i < 4; i++)
#pragma unroll
        for (int j = 0; j < 4; j++) acc[i][j] = 0.0f;

#pragma unroll 16
    for (int k = 0; k < D; k++) {
        float4 a  = *(const float4*)&As[k][r0];
        float4 bv = *(const float4*)&Bs[k][c0];
        float av[4] = {a.x, a.y, a.z, a.w};
        float bw[4] = {bv.x, bv.y, bv.z, bv.w};
#pragma unroll
        for (int i = 0; i < 4; i++)
#pragma unroll
            for (int j = 0; j < 4; j++)
                acc[i][j] = fmaf(av[i], bw[j], acc[i][j]);
    }

    float sc = scale_p[0];
    const float ONE_EPS = 1.0f + 1e-7f;  // rounds to 1 + ulp, matching jnp

#pragma unroll
    for (int i = 0; i < 4; i++) {
        float xi = sx2i[r0 + i];
        float ri = sri[r0 + i];
        float res[4];
#pragma unroll
        for (int j = 0; j < 4; j++) {
            float sq  = fmaxf(xi + sx2j[c0 + j] - 2.0f * acc[i][j], 0.0f);
            float x   = 2.0f * sq * (ri * srj[c0 + j]);
            float arg = 1.0f + x;                 // replicate reference fp32 rounding
            arg = fmaxf(arg, ONE_EPS);            // replicate reference clamp
            float xe = arg - 1.0f;                // exact for arg < 2 (Sterbenz)
            // stable acosh(1+xe) = log1p(xe + sqrt(xe*(xe+2)))
            float tt   = xe + sqrtf(fmaf(xe, xe, 2.0f * xe));
            float dist = log1pf(tt);
            res[j] = -sc * dist;
        }
        float4 o;
        o.x = res[0]; o.y = res[1]; o.z = res[2]; o.w = res[3];
        *(float4*)(out + (size_t)b * S * S + (size_t)(i0 + r0 + i) * S + j0 + c0) = o;
    }
}

// ---------------------------------------------------------------------------
extern "C" void kernel_launch(void* const* d_in, const int* in_sizes, int n_in,
                              void* d_out, int out_size) {
    const void*  ids     = d_in[0];
    const float* W       = (const float*)d_in[1];
    const float* scale_p = (const float*)d_in[2];
    float* out = (float*)d_out;

    int n_ids   = in_sizes[0];            // B*S = 4096
    int num_tok = in_sizes[1] / D;        // 30522
    int S       = out_size / n_ids;       // 1024
    int B       = n_ids / S;              // 4

    detect_kernel<<<1, 256>>>((const int*)ids, n_ids);

    int prep_blocks = (n_ids + 7) / 8;    // 8 warps per 256-thread block
    prep_kernel<<<prep_blocks, 256>>>(ids, W, n_ids, num_tok);

    dim3 grid(S / 64, S / 64, B);
    bias_kernel<<<grid, 256>>>(scale_p, out, S);
}

// round 2
// speedup vs baseline: 1.1391x; 1.1391x over previous
#include <cuda_runtime.h>

#define D 64
#define MAX_TOKENS 4096
#define LDA 132   // 128 + 4 pad (floats), keeps 16B alignment per k-row

// Scratch (no cudaMalloc allowed)
__device__ float g_emb[MAX_TOKENS * D];
__device__ float g_x2[MAX_TOKENS];
__device__ float g_rinv[MAX_TOKENS];

// ---------------------------------------------------------------------------
// f32x2 packed helpers (sm_103a)
// ---------------------------------------------------------------------------
__device__ __forceinline__ unsigned long long pk2(float lo, float hi) {
    unsigned long long r;
    asm("mov.b64 %0, {%1,%2};" : "=l"(r) : "f"(lo), "f"(hi));
    return r;
}
__device__ __forceinline__ void fma2(unsigned long long& d,
                                     unsigned long long a,
                                     unsigned long long b) {
    asm("fma.rn.f32x2 %0, %1, %2, %0;" : "+l"(d) : "l"(a), "l"(b));
}
__device__ __forceinline__ float2 upk2(unsigned long long v) {
    float2 r;
    asm("mov.b64 {%0,%1}, %2;" : "=f"(r.x), "=f"(r.y) : "l"(v));
    return r;
}

// ---------------------------------------------------------------------------
// Prep: detect id dtype (block-local, consistent: global property of buffer),
// gather embedding rows, project to Poincare ball, compute x2 and 1/(1-x2).
// One warp per token, 8 tokens per 256-thread block.
// ---------------------------------------------------------------------------
__global__ __launch_bounds__(256)
void prep_kernel(const void* __restrict__ ids_raw,
                 const float* __restrict__ W,
                 int n_ids, int num_tok) {
    // int64 little-endian with ids < 2^31 => every odd 32-bit word is 0.
    // Scan only the first n_ids words (safe for both layouts).
    const int* w32 = (const int*)ids_raw;
    int any = 0;
    for (int i = threadIdx.x * 2 + 1; i < n_ids; i += 2 * blockDim.x)
        any |= w32[i];
    int is64 = (__syncthreads_or(any) == 0);

    int warp = (blockIdx.x * blockDim.x + threadIdx.x) >> 5;
    int lane = threadIdx.x & 31;
    if (warp >= n_ids) return;

    long long id = is64 ? ((const long long*)ids_raw)[warp]
                        : (long long)w32[warp];
    if (id < 0) id = 0;
    if (id > (long long)(num_tok - 1)) id = num_tok - 1;

    const float* row = W + (size_t)id * D;
    float v0 = row[lane];
    float v1 = row[lane + 32];
    float s = v0 * v0 + v1 * v1;
#pragma unroll
    for (int o = 16; o; o >>= 1) s += __shfl_xor_sync(0xffffffffu, s, o);

    const float max_norm = 1.0f - 1e-5f;
    float norm = sqrtf(s);
    float f = (norm > max_norm) ? (max_norm / fmaxf(norm, 1e-12f)) : 1.0f;
    v0 *= f; v1 *= f;

    g_emb[warp * D + lane]      = v0;
    g_emb[warp * D + lane + 32] = v1;

    float s2 = v0 * v0 + v1 * v1;
#pragma unroll
    for (int o = 16; o; o >>= 1) s2 += __shfl_xor_sync(0xffffffffu, s2, o);

    if (lane == 0) {
        g_x2[warp]   = s2;
        g_rinv[warp] = 1.0f / (1.0f - s2);
    }
}

// ---------------------------------------------------------------------------
// Per-element epilogue: stable acosh with approx sqrt + fast log.
// ---------------------------------------------------------------------------
__device__ __forceinline__ float bias_elt(float xi, float ri, float xjv,
                                          float rjv, float g, float sc) {
    float sq  = fmaxf(xi + xjv - 2.0f * g, 0.0f);
    float x   = 2.0f * sq * (ri * rjv);
    float arg = 1.0f + x;                        // reference fp32 rounding
    arg = fmaxf(arg, 1.0f + 1e-7f);              // reference clamp (1 + ulp)
    float xe = arg - 1.0f;                       // exact (Sterbenz) for arg < 2
    float prod = fmaf(xe, xe, 2.0f * xe);        // xe*(xe+2)
    float s;
    asm("sqrt.approx.f32 %0, %1;" : "=f"(s) : "f"(prod));
    float dist = __logf(1.0f + (xe + s));        // acosh(1+xe)
    return -sc * dist;
}

// ---------------------------------------------------------------------------
// Main: 128x128 output tile per CTA, 256 threads, 8x8 microtile, FFMA2.
// smem k-major so inner loop is 4 x LDS.128 + 32 FFMA2 per k.
// ---------------------------------------------------------------------------
__global__ __launch_bounds__(256)
void bias_kernel(const float* __restrict__ scale_p,
                 float* __restrict__ out, int S) {
    extern __shared__ float sm[];
    float* As   = sm;               // 64 * LDA
    float* Bs   = sm + 64 * LDA;    // 64 * LDA
    float* sx2i = Bs + 64 * LDA;    // 128
    float* sri  = sx2i + 128;
    float* sx2j = sri + 128;
    float* srj  = sx2j + 128;

    int b  = blockIdx.z;
    int i0 = blockIdx.y * 128;
    int j0 = blockIdx.x * 128;
    int base = b * S;
    int t = threadIdx.x;

    // Load + transpose the two 128x64 tiles into k-major smem.
    {
        int row = t >> 1, half = t & 1;
        const float4* ap = (const float4*)(g_emb + (size_t)(base + i0 + row) * D + half * 32);
        const float4* bp = (const float4*)(g_emb + (size_t)(base + j0 + row) * D + half * 32);
#pragma unroll
        for (int q = 0; q < 8; q++) {
            float4 va = ap[q];
            int k = half * 32 + q * 4;
            As[(k + 0) * LDA + row] = va.x; As[(k + 1) * LDA + row] = va.y;
            As[(k + 2) * LDA + row] = va.z; As[(k + 3) * LDA + row] = va.w;
        }
#pragma unroll
        for (int q = 0; q < 8; q++) {
            float4 vb = bp[q];
            int k = half * 32 + q * 4;
            Bs[(k + 0) * LDA + row] = vb.x; Bs[(k + 1) * LDA + row] = vb.y;
            Bs[(k + 2) * LDA + row] = vb.z; Bs[(k + 3) * LDA + row] = vb.w;
        }
        if (t < 128) {
            sx2i[t] = g_x2[base + i0 + t];
            sri[t]  = g_rinv[base + i0 + t];
        } else {
            int u = t - 128;
            sx2j[u] = g_x2[base + j0 + u];
            srj[u]  = g_rinv[base + j0 + u];
        }
    }
    __syncthreads();

    int tx = t & 15, ty = t >> 4;
    int r0 = ty * 8, c0 = tx * 8;

    unsigned long long acc[4][8];   // acc[ip][j] = (gram[2ip][j], gram[2ip+1][j])
#pragma unroll
    for (int i = 0; i < 4; i++)
#pragma unroll
        for (int j = 0; j < 8; j++) acc[i][j] = 0ull;

#pragma unroll 8
    for (int k = 0; k < D; k++) {
        const float4* A4 = (const float4*)(As + k * LDA + r0);
        const float4* B4 = (const float4*)(Bs + k * LDA + c0);
        float4 a0 = A4[0], a1 = A4[1];
        float4 b0 = B4[0], b1 = B4[1];
        unsigned long long ap0 = pk2(a0.x, a0.y);
        unsigned long long ap1 = pk2(a0.z, a0.w);
        unsigned long long ap2 = pk2(a1.x, a1.y);
        unsigned long long ap3 = pk2(a1.z, a1.w);
        unsigned long long bp[8];
        bp[0] = pk2(b0.x, b0.x); bp[1] = pk2(b0.y, b0.y);
        bp[2] = pk2(b0.z, b0.z); bp[3] = pk2(b0.w, b0.w);
        bp[4] = pk2(b1.x, b1.x); bp[5] = pk2(b1.y, b1.y);
        bp[6] = pk2(b1.z, b1.z); bp[7] = pk2(b1.w, b1.w);
#pragma unroll
        for (int j = 0; j < 8; j++) {
            fma2(acc[0][j], ap0, bp[j]);
            fma2(acc[1][j], ap1, bp[j]);
            fma2(acc[2][j], ap2, bp[j]);
            fma2(acc[3][j], ap3, bp[j]);
        }
    }

    float sc = scale_p[0];
    float xj[8], rj[8];
#pragma unroll
    for (int j = 0; j < 8; j++) { xj[j] = sx2j[c0 + j]; rj[j] = srj[c0 + j]; }

    size_t outcol = (size_t)b * S * S + (size_t)j0 + c0;
#pragma unroll
    for (int ip = 0; ip < 4; ip++) {
        float xi0 = sx2i[r0 + 2 * ip],     ri0 = sri[r0 + 2 * ip];
        float xi1 = sx2i[r0 + 2 * ip + 1], ri1 = sri[r0 + 2 * ip + 1];
        float res0[8], res1[8];
#pragma unroll
        for (int j = 0; j < 8; j++) {
            float2 g = upk2(acc[ip][j]);
            res0[j] = bias_elt(xi0, ri0, xj[j], rj[j], g.x, sc);
            res1[j] = bias_elt(xi1, ri1, xj[j], rj[j], g.y, sc);
        }
        float* o0 = out + outcol + (size_t)(i0 + r0 + 2 * ip) * S;
        float* o1 = o0 + S;
        ((float4*)o0)[0] = make_float4(res0[0], res0[1], res0[2], res0[3]);
        ((float4*)o0)[1] = make_float4(res0[4], res0[5], res0[6], res0[7]);
        ((float4*)o1)[0] = make_float4(res1[0], res1[1], res1[2], res1[3]);
        ((float4*)o1)[1] = make_float4(res1[4], res1[5], res1[6], res1[7]);
    }
}

// ---------------------------------------------------------------------------
extern "C" void kernel_launch(void* const* d_in, const int* in_sizes, int n_in,
                              void* d_out, int out_size) {
    const void*  ids     = d_in[0];
    const float* W       = (const float*)d_in[1];
    const float* scale_p = (const float*)d_in[2];
    float* out = (float*)d_out;

    int n_ids   = in_sizes[0];            // B*S = 4096
    int num_tok = in_sizes[1] / D;        // 30522
    int S       = out_size / n_ids;       // 1024
    int B       = n_ids / S;              // 4

    int prep_blocks = (n_ids + 7) / 8;    // 8 warps per 256-thread block
    prep_kernel<<<prep_blocks, 256>>>(ids, W, n_ids, num_tok);

    int smem_bytes = (2 * 64 * LDA + 4 * 128) * (int)sizeof(float);  // ~69.6 KB
    static int attr_set = 0;
    if (!attr_set) {
        cudaFuncSetAttribute(bias_kernel,
                             cudaFuncAttributeMaxDynamicSharedMemorySize,
                             smem_bytes);
        attr_set = 1;
    }

    dim3 grid(S / 128, S / 128, B);
    bias_kernel<<<grid, 256, smem_bytes>>>(scale_p, out, S);
}

// round 4
// speedup vs baseline: 1.7703x; 1.5541x over previous
#include <cuda_runtime.h>
#include <cuda_bf16.h>
#include <cstdint>

#define D 64
#define MAX_TOKENS 4096

// Scratch (no cudaMalloc allowed)
__device__ __align__(16) __nv_bfloat16 g_hi[MAX_TOKENS * D];
__device__ __align__(16) __nv_bfloat16 g_lo[MAX_TOKENS * D];
__device__ float g_x2[MAX_TOKENS];
__device__ float g_rinv[MAX_TOKENS];

// ---------------------------------------------------------------------------
// helpers
// ---------------------------------------------------------------------------
__device__ __forceinline__ uint32_t smem_u32(const void* p) {
    uint32_t a;
    asm("{ .reg .u64 t; cvta.to.shared.u64 t, %1; cvt.u32.u64 %0, t; }"
        : "=r"(a) : "l"(p));
    return a;
}
__device__ __forceinline__ void ldsm_x4(uint32_t& r0, uint32_t& r1,
                                        uint32_t& r2, uint32_t& r3,
                                        uint32_t addr) {
    asm volatile("ldmatrix.sync.aligned.m8n8.x4.shared.b16 {%0,%1,%2,%3}, [%4];"
                 : "=r"(r0), "=r"(r1), "=r"(r2), "=r"(r3) : "r"(addr));
}
__device__ __forceinline__ void ldsm_x2(uint32_t& r0, uint32_t& r1,
                                        uint32_t addr) {
    asm volatile("ldmatrix.sync.aligned.m8n8.x2.shared.b16 {%0,%1}, [%2];"
                 : "=r"(r0), "=r"(r1) : "r"(addr));
}
__device__ __forceinline__ void mma16816(float* d, const uint32_t* a,
                                         const uint32_t* b) {
    asm volatile(
        "mma.sync.aligned.m16n8k16.row.col.f32.bf16.bf16.f32 "
        "{%0,%1,%2,%3}, {%4,%5,%6,%7}, {%8,%9}, {%0,%1,%2,%3};"
        : "+f"(d[0]), "+f"(d[1]), "+f"(d[2]), "+f"(d[3])
        : "r"(a[0]), "r"(a[1]), "r"(a[2]), "r"(a[3]), "r"(b[0]), "r"(b[1]));
}

// ---------------------------------------------------------------------------
// Prep: id-dtype detect, gather, project, x2, 1/(1-x2), bf16 hi/lo split.
// One warp per token.
// ---------------------------------------------------------------------------
__global__ __launch_bounds__(256)
void prep_kernel(const void* __restrict__ ids_raw,
                 const float* __restrict__ W,
                 int n_ids, int num_tok) {
    const int* w32 = (const int*)ids_raw;
    int any = 0;
    for (int i = threadIdx.x * 2 + 1; i < n_ids; i += 2 * blockDim.x)
        any |= w32[i];
    int is64 = (__syncthreads_or(any) == 0);

    int warp = (blockIdx.x * blockDim.x + threadIdx.x) >> 5;
    int lane = threadIdx.x & 31;
    if (warp >= n_ids) return;

    long long id = is64 ? ((const long long*)ids_raw)[warp]
                        : (long long)w32[warp];
    if (id < 0) id = 0;
    if (id > (long long)(num_tok - 1)) id = num_tok - 1;

    const float* row = W + (size_t)id * D;
    float v0 = row[lane];
    float v1 = row[lane + 32];
    float s = v0 * v0 + v1 * v1;
#pragma unroll
    for (int o = 16; o; o >>= 1) s += __shfl_xor_sync(0xffffffffu, s, o);

    const float max_norm = 1.0f - 1e-5f;
    float norm = sqrtf(s);
    float f = (norm > max_norm) ? (max_norm / fmaxf(norm, 1e-12f)) : 1.0f;
    v0 *= f; v1 *= f;

    __nv_bfloat16 h0 = __float2bfloat16_rn(v0);
    __nv_bfloat16 h1 = __float2bfloat16_rn(v1);
    g_hi[warp * D + lane]      = h0;
    g_hi[warp * D + lane + 32] = h1;
    g_lo[warp * D + lane]      = __float2bfloat16_rn(v0 - __bfloat162float(h0));
    g_lo[warp * D + lane + 32] = __float2bfloat16_rn(v1 - __bfloat162float(h1));

    float s2 = v0 * v0 + v1 * v1;
#pragma unroll
    for (int o = 16; o; o >>= 1) s2 += __shfl_xor_sync(0xffffffffu, s2, o);

    if (lane == 0) {
        g_x2[warp]   = s2;
        g_rinv[warp] = 1.0f / (1.0f - s2);
    }
}

// ---------------------------------------------------------------------------
// Epilogue element
// ---------------------------------------------------------------------------
__device__ __forceinline__ float bias_elt(float xi, float ri, float xjv,
                                          float rjv, float g, float sc) {
    float sq  = fmaxf(xi + xjv - 2.0f * g, 0.0f);
    float x   = 2.0f * sq * (ri * rjv);
    float arg = 1.0f + x;
    arg = fmaxf(arg, 1.0f + 1e-7f);
    float xe = arg - 1.0f;
    float prod = fmaf(xe, xe, 2.0f * xe);
    float s;
    asm("sqrt.approx.f32 %0, %1;" : "=f"(s) : "f"(prod));
    float dist = __logf(1.0f + (xe + s));
    return -sc * dist;
}

// ---------------------------------------------------------------------------
// Main: 128x128 tile per CTA via mma.sync bf16 (hi/lo split, 3 products).
// Smem tiles: row-major [token][k] bf16, 144B row pitch (ldmatrix
// conflict-free). 8 warps in 2(m) x 4(n); warp tile 64x32.
// ---------------------------------------------------------------------------
#define LDB     144                     // bytes per smem tile row
#define T_AH    0                       // i-block hi
#define T_AL    (128 * LDB)             // i-block lo
#define T_BH    (2 * 128 * LDB)         // j-block hi
#define T_BL    (3 * 128 * LDB)         // j-block lo
#define O_X2I   (4 * 128 * LDB)
#define O_RI    (O_X2I + 512)
#define O_X2J   (O_RI + 512)
#define O_RJ    (O_X2J + 512)
#define SMEM_TOT (O_RJ + 512)           // 75776 bytes

__global__ __launch_bounds__(256, 2)
void bias_kernel(const float* __restrict__ scale_p,
                 float* __restrict__ out, int S) {
    extern __shared__ char sm[];
    uint32_t sb = smem_u32(sm);

    int b  = blockIdx.z;
    int i0 = blockIdx.y * 128;
    int j0 = blockIdx.x * 128;
    int base = b * S;
    int t = threadIdx.x;
    int wid = t >> 5, lane = t & 31;

    // ---- stage tiles: 128 rows x 64 bf16 (128B) -> smem pitch 144B ----
    {
        const __nv_bfloat16* srcs[4] = {
            g_hi + (size_t)(base + i0) * D, g_lo + (size_t)(base + i0) * D,
            g_hi + (size_t)(base + j0) * D, g_lo + (size_t)(base + j0) * D};
        const int offs[4] = {T_AH, T_AL, T_BH, T_BL};
#pragma unroll
        for (int m = 0; m < 4; m++) {
            const uint4* src = (const uint4*)srcs[m];
#pragma unroll
            for (int it = 0; it < 4; it++) {
                int idx = t + it * 256;        // 0..1023
                int row = idx >> 3, ch = idx & 7;
                uint4 v = src[row * 8 + ch];
                *(uint4*)(sm + offs[m] + row * LDB + ch * 16) = v;
            }
        }
        if (t < 128) {
            ((float*)(sm + O_X2I))[t] = g_x2[base + i0 + t];
            ((float*)(sm + O_RI))[t]  = g_rinv[base + i0 + t];
        } else {
            int u = t - 128;
            ((float*)(sm + O_X2J))[u] = g_x2[base + j0 + u];
            ((float*)(sm + O_RJ))[u]  = g_rinv[base + j0 + u];
        }
    }
    __syncthreads();

    int wm = wid >> 2;          // 0..1  (m block of 64)
    int wn = wid & 3;           // 0..3  (n block of 32)

    float acc[4][4][4];
#pragma unroll
    for (int mt = 0; mt < 4; mt++)
#pragma unroll
        for (int nt = 0; nt < 4; nt++)
#pragma unroll
            for (int r = 0; r < 4; r++) acc[mt][nt][r] = 0.0f;

    // ldmatrix per-lane address pieces
    int lm = lane >> 3, lr = lane & 7;          // matrix idx, row in matrix
    // A (x4): row = wm*64 + mt*16 + (lm&1)*8 + lr ; kbyte = ks*32 + (lm>>1)*16
    int a_row = wm * 64 + (lm & 1) * 8 + lr;
    int a_kb  = (lm >> 1) * 16;
    // B (x2, lanes 0-15): row = wn*32 + nt*8 + lr ; kbyte = ks*32 + lm*16
    int bl = lane & 15;
    int b_row = wn * 32 + (bl & 7);
    int b_kb  = (bl >> 3) * 16;

    const int passA[3] = {T_AH, T_AH, T_AL};
    const int passB[3] = {T_BH, T_BL, T_BH};

#pragma unroll
    for (int p = 0; p < 3; p++) {
        uint32_t aBase = sb + passA[p] + a_row * LDB + a_kb;
        uint32_t bBase = sb + passB[p] + b_row * LDB + b_kb;
#pragma unroll
        for (int ks = 0; ks < 4; ks++) {
            uint32_t a[4][4], bf[4][2];
#pragma unroll
            for (int mt = 0; mt < 4; mt++)
                ldsm_x4(a[mt][0], a[mt][1], a[mt][2], a[mt][3],
                        aBase + mt * 16 * LDB + ks * 32);
#pragma unroll
            for (int nt = 0; nt < 4; nt++)
                ldsm_x2(bf[nt][0], bf[nt][1],
                        bBase + nt * 8 * LDB + ks * 32);
#pragma unroll
            for (int mt = 0; mt < 4; mt++)
#pragma unroll
                for (int nt = 0; nt < 4; nt++)
                    mma16816(acc[mt][nt], a[mt], bf[nt]);
        }
    }

    // ---- epilogue ----
    float sc = scale_p[0];
    int g  = lane >> 2;          // 0..7
    int tq = lane & 3;           // 0..3
    const float* sx2i = (const float*)(sm + O_X2I);
    const float* sri  = (const float*)(sm + O_RI);
    const float* sx2j = (const float*)(sm + O_X2J);
    const float* srj  = (const float*)(sm + O_RJ);

#pragma unroll
    for (int mt = 0; mt < 4; mt++) {
        int i_a = wm * 64 + mt * 16 + g;
        int i_b = i_a + 8;
        float xia = sx2i[i_a], ria = sri[i_a];
        float xib = sx2i[i_b], rib = sri[i_b];
        size_t rowA = (size_t)b * S * S + (size_t)(i0 + i_a) * S + j0;
        size_t rowB = rowA + 8u * S;
#pragma unroll
        for (int nt = 0; nt < 4; nt++) {
            int j_c = wn * 32 + nt * 8 + 2 * tq;
            float xj0 = sx2j[j_c],     rj0 = srj[j_c];
            float xj1 = sx2j[j_c + 1], rj1 = srj[j_c + 1];
            float2 oA, oB;
            oA.x = bias_elt(xia, ria, xj0, rj0, acc[mt][nt][0], sc);
            oA.y = bias_elt(xia, ria, xj1, rj1, acc[mt][nt][1], sc);
            oB.x = bias_elt(xib, rib, xj0, rj0, acc[mt][nt][2], sc);
            oB.y = bias_elt(xib, rib, xj1, rj1, acc[mt][nt][3], sc);
            *(float2*)(out + rowA + j_c) = oA;
            *(float2*)(out + rowB + j_c) = oB;
        }
    }
}

// ---------------------------------------------------------------------------
extern "C" void kernel_launch(void* const* d_in, const int* in_sizes, int n_in,
                              void* d_out, int out_size) {
    const void*  ids     = d_in[0];
    const float* W       = (const float*)d_in[1];
    const float* scale_p = (const float*)d_in[2];
    float* out = (float*)d_out;

    int n_ids   = in_sizes[0];            // B*S = 4096
    int num_tok = in_sizes[1] / D;        // 30522
    int S       = out_size / n_ids;       // 1024
    int B       = n_ids / S;              // 4

    int prep_blocks = (n_ids + 7) / 8;
    prep_kernel<<<prep_blocks, 256>>>(ids, W, n_ids, num_tok);

    static int attr_set = 0;
    if (!attr_set) {
        cudaFuncSetAttribute(bias_kernel,
                             cudaFuncAttributeMaxDynamicSharedMemorySize,
                             SMEM_TOT);
        attr_set = 1;
    }

    dim3 grid(S / 128, S / 128, B);
    bias_kernel<<<grid, 256, SMEM_TOT>>>(scale_p, out, S);
}